// round 1
// baseline (speedup 1.0000x reference)
#include <cuda_runtime.h>
#include <cuda_bf16.h>

// ---------------------------------------------------------------------------
// MultiHeadAttention baseline (fp32, scalar-pipe tiled SGEMM)
//   X:[B=2,S=2048,D=1024]  Wq/Wk/Wv/Wo:[1024,1024]
//   Q = X@Wq^T ; K = X@Wk^T ; V = X@Wv^T            (4096x1024 each)
//   S = softmax( (Q_h @ K_h^T) / 8 )  per (b,h)     (32 x 2048x2048)
//   O = S @ V_h  -> [B,S,1024] ; out = O @ Wo^T
// ---------------------------------------------------------------------------

#define BATCH   2
#define SEQ     2048
#define DMODEL  1024
#define HEADS   16
#define KDIM    64
#define MTOT    (BATCH * SEQ)           // 4096

// Scratch (device globals; allocation-free). Small padding to be safe.
__device__ float g_Q[MTOT * DMODEL + 256];
__device__ float g_K[MTOT * DMODEL + 256];
__device__ float g_V[MTOT * DMODEL + 256];
__device__ float g_O[MTOT * DMODEL + 256];
__device__ float g_S[(size_t)BATCH * HEADS * SEQ * SEQ + 256];   // 512 MB scores

// ---------------------------------------------------------------------------
// Generic batched tiled GEMM:
//   C[m,n] = alpha * sum_k A[m,k] * (TRANS_B ? B[n,k] : B[k,n])
// Batch index bz decomposed: outer = bz / inner, in = bz % inner,
// pointer offsets = outer*sXo + in*sXi.
// BM=BN=128, BK=8, 256 threads, 8x8 per-thread microtile.
// ---------------------------------------------------------------------------
#define BM 128
#define BN 128
#define BK 8
#define TM 8
#define TN 8

template <bool TRANS_B>
__global__ __launch_bounds__(256)
void gemm_kernel(const float* __restrict__ A, const float* __restrict__ B,
                 float* __restrict__ C,
                 int M, int N, int K, int lda, int ldb, int ldc, float alpha,
                 int inner,
                 long sAo, long sAi, long sBo, long sBi, long sCo, long sCi)
{
    const int bz = blockIdx.z;
    const int bo = bz / inner;
    const int bi = bz % inner;
    A += bo * sAo + bi * sAi;
    B += bo * sBo + bi * sBi;
    C += bo * sCo + bi * sCi;

    __shared__ float As[BK][BM];
    __shared__ float Bs[BK][BN];

    const int tid  = threadIdx.x;
    const int m0   = blockIdx.y * BM;
    const int n0   = blockIdx.x * BN;
    const int trow = tid / 16;       // 0..15
    const int tcol = tid % 16;       // 0..15

    float acc[TM][TN];
    #pragma unroll
    for (int i = 0; i < TM; i++)
        #pragma unroll
        for (int j = 0; j < TN; j++) acc[i][j] = 0.f;

    for (int k0 = 0; k0 < K; k0 += BK) {
        // ---- load A tile: 128 rows x 8 k (scalar, guarded) ----
        {
            const int row = tid >> 1;            // 0..127
            const int kk  = (tid & 1) * 4;       // 0 or 4
            const int gm  = m0 + row;
            #pragma unroll
            for (int i = 0; i < 4; i++) {
                const int gk = k0 + kk + i;
                float v = 0.f;
                if (gm < M && gk < K) v = A[(long)gm * lda + gk];
                As[kk + i][row] = v;
            }
        }
        // ---- load B tile ----
        if (TRANS_B) {
            const int row = tid >> 1;            // n index 0..127
            const int kk  = (tid & 1) * 4;
            const int gn  = n0 + row;
            #pragma unroll
            for (int i = 0; i < 4; i++) {
                const int gk = k0 + kk + i;
                float v = 0.f;
                if (gn < N && gk < K) v = B[(long)gn * ldb + gk];
                Bs[kk + i][row] = v;
            }
        } else {
            const int kk = tid >> 5;             // 0..7
            const int nn = (tid & 31) * 4;       // 0..124
            const int gk = k0 + kk;
            #pragma unroll
            for (int i = 0; i < 4; i++) {
                const int gn = n0 + nn + i;
                float v = 0.f;
                if (gk < K && gn < N) v = B[(long)gk * ldb + gn];
                Bs[kk][nn + i] = v;
            }
        }
        __syncthreads();

        // ---- compute ----
        #pragma unroll
        for (int k = 0; k < BK; k++) {
            float a[TM], b[TN];
            const float4 a0 = *reinterpret_cast<const float4*>(&As[k][trow * TM]);
            const float4 a1 = *reinterpret_cast<const float4*>(&As[k][trow * TM + 4]);
            const float4 b0 = *reinterpret_cast<const float4*>(&Bs[k][tcol * TN]);
            const float4 b1 = *reinterpret_cast<const float4*>(&Bs[k][tcol * TN + 4]);
            a[0]=a0.x; a[1]=a0.y; a[2]=a0.z; a[3]=a0.w;
            a[4]=a1.x; a[5]=a1.y; a[6]=a1.z; a[7]=a1.w;
            b[0]=b0.x; b[1]=b0.y; b[2]=b0.z; b[3]=b0.w;
            b[4]=b1.x; b[5]=b1.y; b[6]=b1.z; b[7]=b1.w;
            #pragma unroll
            for (int i = 0; i < TM; i++)
                #pragma unroll
                for (int j = 0; j < TN; j++)
                    acc[i][j] = fmaf(a[i], b[j], acc[i][j]);
        }
        __syncthreads();
    }

    // ---- store (guarded) ----
    #pragma unroll
    for (int i = 0; i < TM; i++) {
        const int gm = m0 + trow * TM + i;
        if (gm >= M) continue;
        #pragma unroll
        for (int j = 0; j < TN; j++) {
            const int gn = n0 + tcol * TN + j;
            if (gn < N) C[(long)gm * ldc + gn] = alpha * acc[i][j];
        }
    }
}

// ---------------------------------------------------------------------------
// Row softmax over 2048-wide rows. One block (256 threads) per row.
// ---------------------------------------------------------------------------
__global__ __launch_bounds__(256)
void softmax_rows(float* __restrict__ S)
{
    const long row = blockIdx.x;
    float* p = S + row * (long)SEQ;
    const int tid = threadIdx.x;

    float v[8];
    float mx = -1e30f;
    #pragma unroll
    for (int i = 0; i < 8; i++) {
        v[i] = p[tid + i * 256];
        mx = fmaxf(mx, v[i]);
    }
    // block max
    __shared__ float red[32];
    #pragma unroll
    for (int o = 16; o > 0; o >>= 1)
        mx = fmaxf(mx, __shfl_xor_sync(0xFFFFFFFFu, mx, o));
    if ((tid & 31) == 0) red[tid >> 5] = mx;
    __syncthreads();
    if (tid < 32) {
        float m = (tid < 8) ? red[tid] : -1e30f;
        #pragma unroll
        for (int o = 4; o > 0; o >>= 1)
            m = fmaxf(m, __shfl_xor_sync(0xFFFFFFFFu, m, o));
        if (tid == 0) red[0] = m;
    }
    __syncthreads();
    mx = red[0];

    float sum = 0.f;
    #pragma unroll
    for (int i = 0; i < 8; i++) {
        v[i] = __expf(v[i] - mx);
        sum += v[i];
    }
    __syncthreads();
    #pragma unroll
    for (int o = 16; o > 0; o >>= 1)
        sum += __shfl_xor_sync(0xFFFFFFFFu, sum, o);
    if ((tid & 31) == 0) red[tid >> 5] = sum;
    __syncthreads();
    if (tid < 32) {
        float s = (tid < 8) ? red[tid] : 0.f;
        #pragma unroll
        for (int o = 4; o > 0; o >>= 1)
            s += __shfl_xor_sync(0xFFFFFFFFu, s, o);
        if (tid == 0) red[0] = s;
    }
    __syncthreads();
    const float inv = 1.0f / red[0];

    #pragma unroll
    for (int i = 0; i < 8; i++)
        p[tid + i * 256] = v[i] * inv;
}

// ---------------------------------------------------------------------------
extern "C" void kernel_launch(void* const* d_in, const int* in_sizes, int n_in,
                              void* d_out, int out_size)
{
    const float* X  = (const float*)d_in[0];
    const float* Wq = (const float*)d_in[1];
    const float* Wk = (const float*)d_in[2];
    const float* Wv = (const float*)d_in[3];
    const float* Wo = (const float*)d_in[4];
    float* out = (float*)d_out;

    float *Q, *K, *V, *O, *S;
    cudaGetSymbolAddress((void**)&Q, g_Q);
    cudaGetSymbolAddress((void**)&K, g_K);
    cudaGetSymbolAddress((void**)&V, g_V);
    cudaGetSymbolAddress((void**)&O, g_O);
    cudaGetSymbolAddress((void**)&S, g_S);

    const dim3 blk(256);

    // --- 1) Projections: [4096x1024] = X @ W^T ---
    {
        dim3 grid(DMODEL / BN, MTOT / BM, 1);
        gemm_kernel<true><<<grid, blk>>>(X, Wq, Q, MTOT, DMODEL, DMODEL,
                                         DMODEL, DMODEL, DMODEL, 1.0f,
                                         1, 0, 0, 0, 0, 0, 0);
        gemm_kernel<true><<<grid, blk>>>(X, Wk, K, MTOT, DMODEL, DMODEL,
                                         DMODEL, DMODEL, DMODEL, 1.0f,
                                         1, 0, 0, 0, 0, 0, 0);
        gemm_kernel<true><<<grid, blk>>>(X, Wv, V, MTOT, DMODEL, DMODEL,
                                         DMODEL, DMODEL, DMODEL, 1.0f,
                                         1, 0, 0, 0, 0, 0, 0);
    }

    // --- 2) Scores: per (b,h): S = (Q_h @ K_h^T) * 0.125 ---
    {
        dim3 grid(SEQ / BN, SEQ / BM, BATCH * HEADS);
        const long sQb = (long)SEQ * DMODEL;   // per-batch
        const long sQh = KDIM;                 // per-head
        const long sSb = (long)HEADS * SEQ * SEQ;
        const long sSh = (long)SEQ * SEQ;
        gemm_kernel<true><<<grid, blk>>>(Q, K, S, SEQ, SEQ, KDIM,
                                         DMODEL, DMODEL, SEQ, 0.125f,
                                         HEADS, sQb, sQh, sQb, sQh, sSb, sSh);
    }

    // --- 3) Softmax over last dim ---
    {
        const long nrows = (long)BATCH * HEADS * SEQ;   // 65536
        softmax_rows<<<(unsigned)nrows, blk>>>(S);
    }

    // --- 4) O_h = S @ V_h  (N = 64) ---
    {
        dim3 grid(1, SEQ / BM, BATCH * HEADS);
        const long sSb = (long)HEADS * SEQ * SEQ;
        const long sSh = (long)SEQ * SEQ;
        const long sVb = (long)SEQ * DMODEL;
        const long sVh = KDIM;
        gemm_kernel<false><<<grid, blk>>>(S, V, O, SEQ, KDIM, SEQ,
                                          SEQ, DMODEL, DMODEL, 1.0f,
                                          HEADS, sSb, sSh, sVb, sVh, sVb, sVh);
    }

    // --- 5) out = O @ Wo^T ---
    {
        dim3 grid(DMODEL / BN, MTOT / BM, 1);
        gemm_kernel<true><<<grid, blk>>>(O, Wo, out, MTOT, DMODEL, DMODEL,
                                         DMODEL, DMODEL, DMODEL, 1.0f,
                                         1, 0, 0, 0, 0, 0, 0);
    }
}

// round 3
// speedup vs baseline: 2.4960x; 2.4960x over previous
#include <cuda_runtime.h>
#include <cuda_bf16.h>
#include <cstdint>

// ---------------------------------------------------------------------------
// MultiHeadAttention via warp-level mma.sync bf16x3 (hi/lo split, fp32 accum)
// (tcgen05 unavailable: harness PTX target is sm_103, not sm_103a)
//   X:[2,2048,1024]  Wq/Wk/Wv/Wo:[1024,1024]
// ---------------------------------------------------------------------------

#define BATCH   2
#define SEQ     2048
#define DMODEL  1024
#define HEADS   16
#define KDIM    64
#define MTOT    (BATCH * SEQ)           // 4096

// Scratch (device globals; allocation-free).
__device__ float g_Q[MTOT * DMODEL + 256];
__device__ float g_K[MTOT * DMODEL + 256];
__device__ float g_V[MTOT * DMODEL + 256];
__device__ float g_O[MTOT * DMODEL + 256];
__device__ float g_S[(size_t)BATCH * HEADS * SEQ * SEQ + 256];   // 512 MB scores

// ======================= helpers ===========================================
__device__ __forceinline__ uint32_t smem_u32_of(const void* p) {
    uint32_t a;
    asm("{ .reg .u64 t; cvta.to.shared.u64 t, %1; cvt.u32.u64 %0, t; }"
        : "=r"(a) : "l"(p));
    return a;
}

__device__ __forceinline__ void ldmatrix_x4(uint32_t* r, uint32_t addr) {
    asm volatile("ldmatrix.sync.aligned.m8n8.x4.shared.b16 {%0,%1,%2,%3}, [%4];"
        : "=r"(r[0]), "=r"(r[1]), "=r"(r[2]), "=r"(r[3]) : "r"(addr));
}

__device__ __forceinline__ void mma_bf16(float* c, const uint32_t* a, const uint32_t* b) {
    asm volatile(
        "mma.sync.aligned.m16n8k16.row.col.f32.bf16.bf16.f32 "
        "{%0,%1,%2,%3}, {%4,%5,%6,%7}, {%8,%9}, {%0,%1,%2,%3};"
        : "+f"(c[0]), "+f"(c[1]), "+f"(c[2]), "+f"(c[3])
        : "r"(a[0]), "r"(a[1]), "r"(a[2]), "r"(a[3]), "r"(b[0]), "r"(b[1]));
}

__device__ __forceinline__ void st128(uint32_t addr, uint32_t a, uint32_t b,
                                      uint32_t c, uint32_t d) {
    asm volatile("st.shared.v4.b32 [%0], {%1,%2,%3,%4};"
                 :: "r"(addr), "r"(a), "r"(b), "r"(c), "r"(d) : "memory");
}

// split two floats into packed bf16 hi pair and lo (residual) pair
__device__ __forceinline__ void split2(float x, float y, uint32_t& hi, uint32_t& lo) {
    __nv_bfloat16 hx = __float2bfloat16(x);
    __nv_bfloat16 hy = __float2bfloat16(y);
    __nv_bfloat162 h; h.x = hx; h.y = hy;
    hi = *reinterpret_cast<uint32_t*>(&h);
    __nv_bfloat162 l = __floats2bfloat162_rn(x - __bfloat162float(hx),
                                             y - __bfloat162float(hy));
    lo = *reinterpret_cast<uint32_t*>(&l);
}

// ======================= warp-MMA GEMM =====================================
// C[m,n] = alpha * sum_k A[m,k] * (TRANS_B ? B[n,k] : B[k,n])
// M-tile 128, N-tile BN_T (128/64), K-chunk 32. 256 threads (8 warps, 4x2).
// SMEM rows padded to 40 bf16 (80 B) -> conflict-free ldmatrix.
#define LDSR 40

template <bool TRANS_B, int BN_T>
__global__ __launch_bounds__(256)
void gemm_mma(const float* __restrict__ A, const float* __restrict__ B,
              float* __restrict__ C,
              int K, int lda, int ldb, int ldc, float alpha, int inner,
              long sAo, long sAi, long sBo, long sBi, long sCo, long sCi)
{
    constexpr int NT8 = BN_T / 16;                  // n8-tiles per warp
    __shared__ __align__(16) uint16_t As_hi[128 * LDSR];
    __shared__ __align__(16) uint16_t As_lo[128 * LDSR];
    __shared__ __align__(16) uint16_t Bs_hi[BN_T * LDSR];
    __shared__ __align__(16) uint16_t Bs_lo[BN_T * LDSR];

    const int bz = blockIdx.z;
    const int bo = bz / inner;
    const int bi = bz % inner;
    A += bo * sAo + bi * sAi;
    B += bo * sBo + bi * sBi;
    C += bo * sCo + bi * sCi;

    const int tid  = threadIdx.x;
    const int wid  = tid >> 5;
    const int lane = tid & 31;
    const int m0   = blockIdx.y * 128;
    const int n0   = blockIdx.x * BN_T;
    const int warp_m = wid & 3;                     // 0..3 -> 32 rows each
    const int warp_n = wid >> 2;                    // 0..1 -> BN_T/2 cols each

    float acc[2][NT8][4];
    #pragma unroll
    for (int i = 0; i < 2; i++)
        #pragma unroll
        for (int j = 0; j < NT8; j++)
            #pragma unroll
            for (int q = 0; q < 4; q++) acc[i][j][q] = 0.f;

    const uint32_t sAhi = smem_u32_of(As_hi), sAlo = smem_u32_of(As_lo);
    const uint32_t sBhi = smem_u32_of(Bs_hi), sBlo = smem_u32_of(Bs_lo);

    for (int k0 = 0; k0 < K; k0 += 32) {
        // ---- A tile: 128 rows x 32 k, hi/lo split ----
        {
            const int r    = tid >> 1;
            const int kseg = (tid & 1) * 16;
            const float* gp = A + (long)(m0 + r) * lda + k0 + kseg;
            uint32_t hi[8], lo[8];
            #pragma unroll
            for (int i = 0; i < 4; i++) {
                float4 v = *reinterpret_cast<const float4*>(gp + i * 4);
                split2(v.x, v.y, hi[2 * i],     lo[2 * i]);
                split2(v.z, v.w, hi[2 * i + 1], lo[2 * i + 1]);
            }
            const uint32_t ad = (uint32_t)(r * LDSR + kseg) * 2;
            st128(sAhi + ad,      hi[0], hi[1], hi[2], hi[3]);
            st128(sAhi + ad + 16, hi[4], hi[5], hi[6], hi[7]);
            st128(sAlo + ad,      lo[0], lo[1], lo[2], lo[3]);
            st128(sAlo + ad + 16, lo[4], lo[5], lo[6], lo[7]);
        }
        // ---- B tile ----
        if (TRANS_B) {
            // B[n,k]: BN_T(=128) rows x 32 k, same pattern as A
            const int r    = tid >> 1;
            const int kseg = (tid & 1) * 16;
            const float* gp = B + (long)(n0 + r) * ldb + k0 + kseg;
            uint32_t hi[8], lo[8];
            #pragma unroll
            for (int i = 0; i < 4; i++) {
                float4 v = *reinterpret_cast<const float4*>(gp + i * 4);
                split2(v.x, v.y, hi[2 * i],     lo[2 * i]);
                split2(v.z, v.w, hi[2 * i + 1], lo[2 * i + 1]);
            }
            const uint32_t ad = (uint32_t)(r * LDSR + kseg) * 2;
            st128(sBhi + ad,      hi[0], hi[1], hi[2], hi[3]);
            st128(sBhi + ad + 16, hi[4], hi[5], hi[6], hi[7]);
            st128(sBlo + ad,      lo[0], lo[1], lo[2], lo[3]);
            st128(sBlo + ad + 16, lo[4], lo[5], lo[6], lo[7]);
        } else {
            // B[k,n] (BN_T=64): transpose to SMEM[n][k] on the fly
            const int kk   = tid >> 3;            // 0..31
            const int nseg = (tid & 7) * 8;       // 0..56
            const float* gp = B + (long)(k0 + kk) * ldb + n0 + nseg;
            float v[8];
            *reinterpret_cast<float4*>(&v[0]) = *reinterpret_cast<const float4*>(gp);
            *reinterpret_cast<float4*>(&v[4]) = *reinterpret_cast<const float4*>(gp + 4);
            #pragma unroll
            for (int j = 0; j < 8; j++) {
                __nv_bfloat16 h = __float2bfloat16(v[j]);
                __nv_bfloat16 l = __float2bfloat16(v[j] - __bfloat162float(h));
                Bs_hi[(nseg + j) * LDSR + kk] = *reinterpret_cast<uint16_t*>(&h);
                Bs_lo[(nseg + j) * LDSR + kk] = *reinterpret_cast<uint16_t*>(&l);
            }
        }
        __syncthreads();

        // ---- compute: 2 k-steps of 16 ----
        #pragma unroll
        for (int ks = 0; ks < 32; ks += 16) {
            uint32_t ah[2][4], al[2][4];
            #pragma unroll
            for (int mi = 0; mi < 2; mi++) {
                const int row = warp_m * 32 + mi * 16 + (lane & 15);
                const int col = ks + (lane >> 4) * 8;
                const uint32_t off = (uint32_t)(row * LDSR + col) * 2;
                ldmatrix_x4(ah[mi], sAhi + off);
                ldmatrix_x4(al[mi], sAlo + off);
            }
            #pragma unroll
            for (int ng = 0; ng < NT8 / 2; ng++) {
                const int nb   = warp_n * (BN_T / 2) + ng * 16;
                const int nrow = nb + (lane & 7) + ((lane >> 4) << 3);
                const int kcol = ks + ((lane >> 3) & 1) * 8;
                const uint32_t off = (uint32_t)(nrow * LDSR + kcol) * 2;
                uint32_t bh[4], bl[4];
                ldmatrix_x4(bh, sBhi + off);
                ldmatrix_x4(bl, sBlo + off);
                #pragma unroll
                for (int mi = 0; mi < 2; mi++) {
                    #pragma unroll
                    for (int nt = 0; nt < 2; nt++) {
                        float* c = acc[mi][ng * 2 + nt];
                        mma_bf16(c, ah[mi], bh + nt * 2);
                        mma_bf16(c, ah[mi], bl + nt * 2);
                        mma_bf16(c, al[mi], bh + nt * 2);
                    }
                }
            }
        }
        __syncthreads();
    }

    // ---- epilogue ----
    const int g  = lane >> 2;
    const int tg = lane & 3;
    #pragma unroll
    for (int mi = 0; mi < 2; mi++) {
        const int row = m0 + warp_m * 32 + mi * 16 + g;
        #pragma unroll
        for (int nt = 0; nt < NT8; nt++) {
            const int col = n0 + warp_n * (BN_T / 2) + nt * 8 + tg * 2;
            float2 v0, v1;
            v0.x = acc[mi][nt][0] * alpha;
            v0.y = acc[mi][nt][1] * alpha;
            v1.x = acc[mi][nt][2] * alpha;
            v1.y = acc[mi][nt][3] * alpha;
            *reinterpret_cast<float2*>(C + (long)row * ldc + col) = v0;
            *reinterpret_cast<float2*>(C + (long)(row + 8) * ldc + col) = v1;
        }
    }
}

// ---------------------------------------------------------------------------
// Row softmax over 2048-wide rows. One block (256 threads) per row.
// ---------------------------------------------------------------------------
__global__ __launch_bounds__(256)
void softmax_rows(float* __restrict__ S)
{
    const long row = blockIdx.x;
    float* p = S + row * (long)SEQ;
    const int tid = threadIdx.x;

    float v[8];
    float mx = -1e30f;
    #pragma unroll
    for (int i = 0; i < 8; i++) {
        v[i] = p[tid + i * 256];
        mx = fmaxf(mx, v[i]);
    }
    __shared__ float red[32];
    #pragma unroll
    for (int o = 16; o > 0; o >>= 1)
        mx = fmaxf(mx, __shfl_xor_sync(0xFFFFFFFFu, mx, o));
    if ((tid & 31) == 0) red[tid >> 5] = mx;
    __syncthreads();
    if (tid < 32) {
        float m = (tid < 8) ? red[tid] : -1e30f;
        #pragma unroll
        for (int o = 4; o > 0; o >>= 1)
            m = fmaxf(m, __shfl_xor_sync(0xFFFFFFFFu, m, o));
        if (tid == 0) red[0] = m;
    }
    __syncthreads();
    mx = red[0];

    float sum = 0.f;
    #pragma unroll
    for (int i = 0; i < 8; i++) {
        v[i] = __expf(v[i] - mx);
        sum += v[i];
    }
    __syncthreads();
    #pragma unroll
    for (int o = 16; o > 0; o >>= 1)
        sum += __shfl_xor_sync(0xFFFFFFFFu, sum, o);
    if ((tid & 31) == 0) red[tid >> 5] = sum;
    __syncthreads();
    if (tid < 32) {
        float s = (tid < 8) ? red[tid] : 0.f;
        #pragma unroll
        for (int o = 4; o > 0; o >>= 1)
            s += __shfl_xor_sync(0xFFFFFFFFu, s, o);
        if (tid == 0) red[0] = s;
    }
    __syncthreads();
    const float inv = 1.0f / red[0];

    #pragma unroll
    for (int i = 0; i < 8; i++)
        p[tid + i * 256] = v[i] * inv;
}

// ---------------------------------------------------------------------------
extern "C" void kernel_launch(void* const* d_in, const int* in_sizes, int n_in,
                              void* d_out, int out_size)
{
    const float* X  = (const float*)d_in[0];
    const float* Wq = (const float*)d_in[1];
    const float* Wk = (const float*)d_in[2];
    const float* Wv = (const float*)d_in[3];
    const float* Wo = (const float*)d_in[4];
    float* out = (float*)d_out;

    float *Q, *K, *V, *O, *S;
    cudaGetSymbolAddress((void**)&Q, g_Q);
    cudaGetSymbolAddress((void**)&K, g_K);
    cudaGetSymbolAddress((void**)&V, g_V);
    cudaGetSymbolAddress((void**)&O, g_O);
    cudaGetSymbolAddress((void**)&S, g_S);

    const dim3 blk(256);

    // --- 1) Projections: [4096x1024] = X @ W^T ---
    {
        dim3 grid(DMODEL / 128, MTOT / 128, 1);
        gemm_mma<true, 128><<<grid, blk>>>(X, Wq, Q, DMODEL,
            DMODEL, DMODEL, DMODEL, 1.0f, 1, 0, 0, 0, 0, 0, 0);
        gemm_mma<true, 128><<<grid, blk>>>(X, Wk, K, DMODEL,
            DMODEL, DMODEL, DMODEL, 1.0f, 1, 0, 0, 0, 0, 0, 0);
        gemm_mma<true, 128><<<grid, blk>>>(X, Wv, V, DMODEL,
            DMODEL, DMODEL, DMODEL, 1.0f, 1, 0, 0, 0, 0, 0, 0);
    }

    // --- 2) Scores: per (b,h): S = (Q_h @ K_h^T) * 0.125 ---
    {
        dim3 grid(SEQ / 128, SEQ / 128, BATCH * HEADS);
        const long sQb = (long)SEQ * DMODEL;
        const long sQh = KDIM;
        const long sSb = (long)HEADS * SEQ * SEQ;
        const long sSh = (long)SEQ * SEQ;
        gemm_mma<true, 128><<<grid, blk>>>(Q, K, S, KDIM,
            DMODEL, DMODEL, SEQ, 0.125f, HEADS, sQb, sQh, sQb, sQh, sSb, sSh);
    }

    // --- 3) Softmax over last dim ---
    softmax_rows<<<(unsigned)((long)BATCH * HEADS * SEQ), blk>>>(S);

    // --- 4) O_h = S @ V_h  (N = 64) ---
    {
        dim3 grid(1, SEQ / 128, BATCH * HEADS);
        const long sSb = (long)HEADS * SEQ * SEQ;
        const long sSh = (long)SEQ * SEQ;
        const long sVb = (long)SEQ * DMODEL;
        const long sVh = KDIM;
        gemm_mma<false, 64><<<grid, blk>>>(S, V, O, SEQ,
            SEQ, DMODEL, DMODEL, 1.0f, HEADS, sSb, sSh, sVb, sVh, sVb, sVh);
    }

    // --- 5) out = O @ Wo^T ---
    {
        dim3 grid(DMODEL / 128, MTOT / 128, 1);
        gemm_mma<true, 128><<<grid, blk>>>(O, Wo, out, DMODEL,
            DMODEL, DMODEL, DMODEL, 1.0f, 1, 0, 0, 0, 0, 0, 0);
    }
}